// round 13
// baseline (speedup 1.0000x reference)
#include <cuda_runtime.h>
#include <stdint.h>

#define N_NODES   50000
#define N_EDGES   640000
#define HIDDEN    128
#define NUM_GRAPHS 50
#define EPS       1e-5f
#define NODES_PER_BLOCK 64
#define EPW       8            // edges per warp in scatter

static_assert(N_EDGES % EPW == 0, "scatter assumes N_EDGES divisible by EPW");

// Scratch (no allocations allowed)
__device__ float g_deg[N_NODES];                 // raw degree
__device__ float g_stat[NUM_GRAPHS * HIDDEN];    // sum, then mu = mean*mean_scale
__device__ float g_stat2[NUM_GRAPHS * HIDDEN];   // sumsq, then A = invstd*weight
__device__ int   g_cnt[NUM_GRAPHS];
__device__ int   g_is64;                         // 1 = int64 indices, 0 = int32

__device__ __forceinline__ int load_idx(const void* p, int i, int is64, int hi)
{
    long long v = is64 ? ((const long long*)p)[i] : (long long)((const int*)p)[i];
    if (v < 0) v = 0;
    if (v > hi) v = hi;
    return (int)v;
}

__device__ __forceinline__ void red_add_v4(float* dst, float4 v)
{
    asm volatile("red.global.add.v4.f32 [%0], {%1,%2,%3,%4};"
                 :: "l"(dst), "f"(v.x), "f"(v.y), "f"(v.z), "f"(v.w) : "memory");
}

// ---------------- init: out = node (float4), zero scratch, detect dtype ----------------
__global__ void k_init(const float4* __restrict__ node, float4* __restrict__ out,
                       const int* __restrict__ ei32)
{
    if (blockIdx.x == 0) {
        int nz = 0;
        for (int k = threadIdx.x; k < 4096; k += blockDim.x)
            if (ei32[2 * k + 1] != 0) nz = 1;
        int any = __syncthreads_count(nz);
        if (threadIdx.x == 0) g_is64 = (any == 0) ? 1 : 0;
    }
    int64_t total = (int64_t)N_NODES * HIDDEN / 4;
    int64_t stride = (int64_t)gridDim.x * blockDim.x;
    for (int64_t j = (int64_t)blockIdx.x * blockDim.x + threadIdx.x; j < total; j += stride) {
        out[j] = node[j];
        if (j < N_NODES) g_deg[j] = 0.0f;
        if (j < NUM_GRAPHS * HIDDEN) { g_stat[j] = 0.0f; g_stat2[j] = 0.0f; }
        if (j < NUM_GRAPHS) g_cnt[j] = 0;
    }
}

// ---------------- degree: deg[col] += edge_attr (4 edges/thread) ----------------
__global__ void k_deg(const void* __restrict__ ei, const float* __restrict__ ea)
{
    int is64 = g_is64;
    int base = (blockIdx.x * blockDim.x + threadIdx.x) * 4;
    #pragma unroll
    for (int k = 0; k < 4; k++) {
        int e = base + k;
        if (e < N_EDGES) {
            int c = load_idx(ei, N_EDGES + e, is64, N_NODES - 1);
            atomicAdd(&g_deg[c], ea[e]);
        }
    }
}

// ---------------- scatter: 8 edges per warp (MLP=8), v4 red, inline rsqrt ----------------
__global__ void k_scatter(const float* __restrict__ node,
                          const void* __restrict__ ei,
                          const float* __restrict__ ea,
                          float* __restrict__ out)
{
    int is64 = g_is64;
    int lane = threadIdx.x & 31;
    int w = blockIdx.x * (blockDim.x >> 5) + (threadIdx.x >> 5);
    int e0 = w * EPW;
    if (e0 >= N_EDGES) return;     // N_EDGES % EPW == 0: all surviving warps full

    int r[EPW], c[EPW];
    float wt[EPW];
    #pragma unroll
    for (int k = 0; k < EPW; k++) {
        r[k] = load_idx(ei, e0 + k, is64, N_NODES - 1);
        c[k] = load_idx(ei, N_EDGES + e0 + k, is64, N_NODES - 1);
    }
    #pragma unroll
    for (int k = 0; k < EPW; k++) {
        float dr = g_deg[r[k]], dc = g_deg[c[k]];
        float ir = dr > 0.0f ? rsqrtf(dr) : 0.0f;
        float ic = dc > 0.0f ? rsqrtf(dc) : 0.0f;
        wt[k] = ir * ea[e0 + k] * ic;
    }

    // front-batched row loads (MLP = EPW)
    float4 v[EPW];
    #pragma unroll
    for (int k = 0; k < EPW; k++)
        v[k] = reinterpret_cast<const float4*>(node + (size_t)r[k] * HIDDEN)[lane];
    #pragma unroll
    for (int k = 0; k < EPW; k++) {
        v[k].x *= wt[k]; v[k].y *= wt[k]; v[k].z *= wt[k]; v[k].w *= wt[k];
        red_add_v4(out + (size_t)c[k] * HIDDEN + lane * 4, v[k]);
    }
}

// ---------------- stats: per-(graph,ch) sum & sumsq, register-accumulated ----------------
__global__ void k_stats(const float* __restrict__ out,
                        const void* __restrict__ batch_ptr)
{
    int is64 = g_is64;
    int ch = threadIdx.x;                       // 0..127
    int n0 = blockIdx.x * NODES_PER_BLOCK;
    int n1 = n0 + NODES_PER_BLOCK;
    if (n1 > N_NODES) n1 = N_NODES;
    if (n0 >= n1) return;

    int   g   = load_idx(batch_ptr, n0, is64, NUM_GRAPHS - 1);
    float s   = 0.0f, s2 = 0.0f;
    int   run = 0;

    for (int n = n0; n < n1; n++) {
        int gn = load_idx(batch_ptr, n, is64, NUM_GRAPHS - 1);
        if (gn != g) {
            atomicAdd(&g_stat[g * HIDDEN + ch], s);
            atomicAdd(&g_stat2[g * HIDDEN + ch], s2);
            if (ch == 0) atomicAdd(&g_cnt[g], run);
            s = 0.0f; s2 = 0.0f; run = 0; g = gn;
        }
        float v = out[(size_t)n * HIDDEN + ch];
        s += v; s2 += v * v; run++;
    }
    atomicAdd(&g_stat[g * HIDDEN + ch], s);
    atomicAdd(&g_stat2[g * HIDDEN + ch], s2);
    if (ch == 0) atomicAdd(&g_cnt[g], run);
}

// ---------------- meanvar: mu = mean*ms, A = rsqrt(var+eps)*weight ----------------
__global__ void k_meanvar(const float* __restrict__ mean_scale,
                          const float* __restrict__ weight)
{
    int i = blockIdx.x * blockDim.x + threadIdx.x;
    if (i < NUM_GRAPHS * HIDDEN) {
        int g = i >> 7, ch = i & 127;
        float cnt  = fmaxf((float)g_cnt[g], 1.0f);
        float mean = g_stat[i] / cnt;
        float e2   = g_stat2[i] / cnt;
        float ms   = mean_scale[ch];
        float var  = fmaxf(e2 - mean * mean * ms * (2.0f - ms), 0.0f);
        g_stat[i]  = mean * ms;
        g_stat2[i] = rsqrtf(var + EPS) * weight[ch];
    }
}

// ---------------- final: out = relu((h - mu) * A + bias), float4, exact grid ----------------
__global__ void k_final(float4* __restrict__ out,
                        const void* __restrict__ batch_ptr,
                        const float4* __restrict__ bias4)
{
    int is64 = g_is64;
    int64_t j = (int64_t)blockIdx.x * blockDim.x + threadIdx.x;
    if (j >= (int64_t)N_NODES * (HIDDEN / 4)) return;
    const float4* mu4 = (const float4*)g_stat;
    const float4* A4  = (const float4*)g_stat2;
    int n  = (int)(j >> 5);
    int c4 = (int)(j & 31);
    int g  = load_idx(batch_ptr, n, is64, NUM_GRAPHS - 1);
    float4 h  = out[j];
    float4 mu = mu4[g * 32 + c4];
    float4 A  = A4[g * 32 + c4];
    float4 b  = bias4[c4];
    h.x = fmaxf((h.x - mu.x) * A.x + b.x, 0.0f);
    h.y = fmaxf((h.y - mu.y) * A.y + b.y, 0.0f);
    h.z = fmaxf((h.z - mu.z) * A.z + b.z, 0.0f);
    h.w = fmaxf((h.w - mu.w) * A.w + b.w, 0.0f);
    out[j] = h;
}

extern "C" void kernel_launch(void* const* d_in, const int* in_sizes, int n_in,
                              void* d_out, int out_size)
{
    // Resolve inputs by element count.
    int idx_node = -1, idx_ei = -1, idx_ea = -1, idx_bp = -1;
    int idx128[3]; int n128 = 0;
    for (int i = 0; i < n_in; i++) {
        switch (in_sizes[i]) {
            case N_NODES * HIDDEN:  idx_node = i; break;
            case 2 * N_EDGES:       idx_ei   = i; break;
            case N_EDGES:           idx_ea   = i; break;
            case N_NODES:           idx_bp   = i; break;
            case HIDDEN:            if (n128 < 3) idx128[n128++] = i; break;
        }
    }
    int idx_w, idx_b, idx_ms;
    if (idx_node >= 0 && idx_bp >= 0 && idx_node > idx_bp) {
        idx_b = idx128[0]; idx_ms = idx128[1]; idx_w = idx128[2];   // alphabetical
    } else {
        idx_w = idx128[0]; idx_b = idx128[1]; idx_ms = idx128[2];   // declaration
    }

    const float* node       = (const float*)d_in[idx_node];
    const void*  edge_index = d_in[idx_ei];
    const float* edge_attr  = (const float*)d_in[idx_ea];
    const void*  batch_ptr  = d_in[idx_bp];
    const float* weight     = (const float*)d_in[idx_w];
    const float* bias       = (const float*)d_in[idx_b];
    const float* mean_scale = (const float*)d_in[idx_ms];
    float* out = (float*)d_out;

    const int64_t NH4 = (int64_t)N_NODES * HIDDEN / 4;   // 1,600,000

    // init + dtype detect
    {
        int threads = 256;
        int blocks = (int)((NH4 + threads - 1) / threads);
        if (blocks > 8192) blocks = 8192;
        k_init<<<blocks, threads>>>((const float4*)node, (float4*)out,
                                    (const int*)edge_index);
    }
    // degree (4 edges/thread)
    k_deg<<<(N_EDGES / 4 + 255) / 256, 256>>>(edge_index, edge_attr);
    // scatter: 512 threads = 16 warps = 128 edges per block
    k_scatter<<<(N_EDGES + 16 * EPW - 1) / (16 * EPW), 512>>>(node, edge_index,
                                                              edge_attr, out);
    // graphnorm
    k_stats<<<(N_NODES + NODES_PER_BLOCK - 1) / NODES_PER_BLOCK, HIDDEN>>>(out, batch_ptr);
    k_meanvar<<<(NUM_GRAPHS * HIDDEN + 255) / 256, 256>>>(mean_scale, weight);
    {
        int threads = 256;
        int blocks = (int)((NH4 + threads - 1) / threads);   // exact cover
        k_final<<<blocks, threads>>>((float4*)out, batch_ptr, (const float4*)bias);
    }
}

// round 14
// speedup vs baseline: 1.0802x; 1.0802x over previous
#include <cuda_runtime.h>
#include <stdint.h>

#define N_NODES   50000
#define N_EDGES   640000
#define HIDDEN    128
#define NUM_GRAPHS 50
#define EPS       1e-5f
#define NODES_PER_BLOCK 64
#define EPW       4            // edges per warp in scatter (measured optimum)

static_assert(N_EDGES % EPW == 0, "scatter assumes N_EDGES divisible by EPW");

// Scratch (no allocations allowed)
__device__ float g_deg[N_NODES];                 // raw degree
__device__ float g_stat[NUM_GRAPHS * HIDDEN];    // sum, then mu = mean*mean_scale
__device__ float g_stat2[NUM_GRAPHS * HIDDEN];   // sumsq, then A = invstd*weight
__device__ int   g_cnt[NUM_GRAPHS];
__device__ int   g_is64;                         // 1 = int64 indices, 0 = int32

__device__ __forceinline__ int load_idx(const void* p, int i, int is64, int hi)
{
    long long v = is64 ? ((const long long*)p)[i] : (long long)((const int*)p)[i];
    if (v < 0) v = 0;
    if (v > hi) v = hi;
    return (int)v;
}

__device__ __forceinline__ void red_add_v4(float* dst, float4 v)
{
    asm volatile("red.global.add.v4.f32 [%0], {%1,%2,%3,%4};"
                 :: "l"(dst), "f"(v.x), "f"(v.y), "f"(v.z), "f"(v.w) : "memory");
}

// ---------------- init: out = node (float4), zero scratch, detect dtype ----------------
__global__ void k_init(const float4* __restrict__ node, float4* __restrict__ out,
                       const int* __restrict__ ei32)
{
    if (blockIdx.x == 0) {
        int nz = 0;
        for (int k = threadIdx.x; k < 4096; k += blockDim.x)
            if (ei32[2 * k + 1] != 0) nz = 1;
        int any = __syncthreads_count(nz);
        if (threadIdx.x == 0) g_is64 = (any == 0) ? 1 : 0;
    }
    int64_t total = (int64_t)N_NODES * HIDDEN / 4;
    int64_t stride = (int64_t)gridDim.x * blockDim.x;
    for (int64_t j = (int64_t)blockIdx.x * blockDim.x + threadIdx.x; j < total; j += stride) {
        out[j] = node[j];
        if (j < N_NODES) g_deg[j] = 0.0f;
        if (j < NUM_GRAPHS * HIDDEN) { g_stat[j] = 0.0f; g_stat2[j] = 0.0f; }
        if (j < NUM_GRAPHS) g_cnt[j] = 0;
    }
}

// ---------------- degree: deg[col] += edge_attr (4 edges/thread) ----------------
__global__ void k_deg(const void* __restrict__ ei, const float* __restrict__ ea)
{
    int is64 = g_is64;
    int base = (blockIdx.x * blockDim.x + threadIdx.x) * 4;
    #pragma unroll
    for (int k = 0; k < 4; k++) {
        int e = base + k;
        if (e < N_EDGES) {
            int c = load_idx(ei, N_EDGES + e, is64, N_NODES - 1);
            atomicAdd(&g_deg[c], ea[e]);
        }
    }
}

// ---------------- scatter: 4 edges per warp (measured optimum), v4 red ----------------
__global__ void k_scatter(const float* __restrict__ node,
                          const void* __restrict__ ei,
                          const float* __restrict__ ea,
                          float* __restrict__ out)
{
    int is64 = g_is64;
    int lane = threadIdx.x & 31;
    int w = blockIdx.x * (blockDim.x >> 5) + (threadIdx.x >> 5);
    int e0 = w * EPW;
    if (e0 >= N_EDGES) return;     // N_EDGES % EPW == 0: all surviving warps full

    int r[EPW], c[EPW];
    float wt[EPW];
    #pragma unroll
    for (int k = 0; k < EPW; k++) {
        r[k] = load_idx(ei, e0 + k, is64, N_NODES - 1);
        c[k] = load_idx(ei, N_EDGES + e0 + k, is64, N_NODES - 1);
    }
    #pragma unroll
    for (int k = 0; k < EPW; k++) {
        float dr = g_deg[r[k]], dc = g_deg[c[k]];
        float ir = dr > 0.0f ? rsqrtf(dr) : 0.0f;
        float ic = dc > 0.0f ? rsqrtf(dc) : 0.0f;
        wt[k] = ir * ea[e0 + k] * ic;
    }

    float4 v[EPW];
    #pragma unroll
    for (int k = 0; k < EPW; k++)
        v[k] = reinterpret_cast<const float4*>(node + (size_t)r[k] * HIDDEN)[lane];
    #pragma unroll
    for (int k = 0; k < EPW; k++) {
        v[k].x *= wt[k]; v[k].y *= wt[k]; v[k].z *= wt[k]; v[k].w *= wt[k];
        red_add_v4(out + (size_t)c[k] * HIDDEN + lane * 4, v[k]);
    }
}

// ---------------- stats: per-(graph,ch) sum & sumsq, register-accumulated ----------------
__global__ void k_stats(const float* __restrict__ out,
                        const void* __restrict__ batch_ptr)
{
    int is64 = g_is64;
    int ch = threadIdx.x;                       // 0..127
    int n0 = blockIdx.x * NODES_PER_BLOCK;
    int n1 = n0 + NODES_PER_BLOCK;
    if (n1 > N_NODES) n1 = N_NODES;
    if (n0 >= n1) return;

    int   g   = load_idx(batch_ptr, n0, is64, NUM_GRAPHS - 1);
    float s   = 0.0f, s2 = 0.0f;
    int   run = 0;

    for (int n = n0; n < n1; n++) {
        int gn = load_idx(batch_ptr, n, is64, NUM_GRAPHS - 1);
        if (gn != g) {
            atomicAdd(&g_stat[g * HIDDEN + ch], s);
            atomicAdd(&g_stat2[g * HIDDEN + ch], s2);
            if (ch == 0) atomicAdd(&g_cnt[g], run);
            s = 0.0f; s2 = 0.0f; run = 0; g = gn;
        }
        float v = out[(size_t)n * HIDDEN + ch];
        s += v; s2 += v * v; run++;
    }
    atomicAdd(&g_stat[g * HIDDEN + ch], s);
    atomicAdd(&g_stat2[g * HIDDEN + ch], s2);
    if (ch == 0) atomicAdd(&g_cnt[g], run);
}

// ---------------- meanvar: mu = mean*ms, A = rsqrt(var+eps)*weight ----------------
__global__ void k_meanvar(const float* __restrict__ mean_scale,
                          const float* __restrict__ weight)
{
    int i = blockIdx.x * blockDim.x + threadIdx.x;
    if (i < NUM_GRAPHS * HIDDEN) {
        int g = i >> 7, ch = i & 127;
        float cnt  = fmaxf((float)g_cnt[g], 1.0f);
        float mean = g_stat[i] / cnt;
        float e2   = g_stat2[i] / cnt;
        float ms   = mean_scale[ch];
        float var  = fmaxf(e2 - mean * mean * ms * (2.0f - ms), 0.0f);
        g_stat[i]  = mean * ms;
        g_stat2[i] = rsqrtf(var + EPS) * weight[ch];
    }
}

// ---------------- final: 2 float4/thread (MLP=2), relu((h-mu)*A+b) ----------------
__global__ void k_final(float4* __restrict__ out,
                        const void* __restrict__ batch_ptr,
                        const float4* __restrict__ bias4)
{
    int is64 = g_is64;
    int64_t t = (int64_t)blockIdx.x * blockDim.x + threadIdx.x;
    int64_t j0 = t * 2;
    if (j0 >= (int64_t)N_NODES * (HIDDEN / 4)) return;
    int64_t j1 = j0 + 1;

    const float4* mu4 = (const float4*)g_stat;
    const float4* A4  = (const float4*)g_stat2;

    // front-batched loads
    float4 h0 = out[j0];
    float4 h1 = out[j1];

    int n0 = (int)(j0 >> 5), c40 = (int)(j0 & 31);
    int n1 = (int)(j1 >> 5), c41 = (int)(j1 & 31);
    int g0 = load_idx(batch_ptr, n0, is64, NUM_GRAPHS - 1);
    int g1 = (n1 == n0) ? g0 : load_idx(batch_ptr, n1, is64, NUM_GRAPHS - 1);

    float4 mu0 = mu4[g0 * 32 + c40], A0 = A4[g0 * 32 + c40], b0 = bias4[c40];
    float4 mu1 = mu4[g1 * 32 + c41], A1 = A4[g1 * 32 + c41], b1 = bias4[c41];

    h0.x = fmaxf((h0.x - mu0.x) * A0.x + b0.x, 0.0f);
    h0.y = fmaxf((h0.y - mu0.y) * A0.y + b0.y, 0.0f);
    h0.z = fmaxf((h0.z - mu0.z) * A0.z + b0.z, 0.0f);
    h0.w = fmaxf((h0.w - mu0.w) * A0.w + b0.w, 0.0f);
    h1.x = fmaxf((h1.x - mu1.x) * A1.x + b1.x, 0.0f);
    h1.y = fmaxf((h1.y - mu1.y) * A1.y + b1.y, 0.0f);
    h1.z = fmaxf((h1.z - mu1.z) * A1.z + b1.z, 0.0f);
    h1.w = fmaxf((h1.w - mu1.w) * A1.w + b1.w, 0.0f);

    out[j0] = h0;
    out[j1] = h1;
}

extern "C" void kernel_launch(void* const* d_in, const int* in_sizes, int n_in,
                              void* d_out, int out_size)
{
    // Resolve inputs by element count.
    int idx_node = -1, idx_ei = -1, idx_ea = -1, idx_bp = -1;
    int idx128[3]; int n128 = 0;
    for (int i = 0; i < n_in; i++) {
        switch (in_sizes[i]) {
            case N_NODES * HIDDEN:  idx_node = i; break;
            case 2 * N_EDGES:       idx_ei   = i; break;
            case N_EDGES:           idx_ea   = i; break;
            case N_NODES:           idx_bp   = i; break;
            case HIDDEN:            if (n128 < 3) idx128[n128++] = i; break;
        }
    }
    int idx_w, idx_b, idx_ms;
    if (idx_node >= 0 && idx_bp >= 0 && idx_node > idx_bp) {
        idx_b = idx128[0]; idx_ms = idx128[1]; idx_w = idx128[2];   // alphabetical
    } else {
        idx_w = idx128[0]; idx_b = idx128[1]; idx_ms = idx128[2];   // declaration
    }

    const float* node       = (const float*)d_in[idx_node];
    const void*  edge_index = d_in[idx_ei];
    const float* edge_attr  = (const float*)d_in[idx_ea];
    const void*  batch_ptr  = d_in[idx_bp];
    const float* weight     = (const float*)d_in[idx_w];
    const float* bias       = (const float*)d_in[idx_b];
    const float* mean_scale = (const float*)d_in[idx_ms];
    float* out = (float*)d_out;

    const int64_t NH4 = (int64_t)N_NODES * HIDDEN / 4;   // 1,600,000

    // init + dtype detect
    {
        int threads = 256;
        int blocks = (int)((NH4 + threads - 1) / threads);
        if (blocks > 8192) blocks = 8192;
        k_init<<<blocks, threads>>>((const float4*)node, (float4*)out,
                                    (const int*)edge_index);
    }
    // degree (4 edges/thread)
    k_deg<<<(N_EDGES / 4 + 255) / 256, 256>>>(edge_index, edge_attr);
    // scatter: 512 threads = 16 warps = 64 edges per block
    k_scatter<<<(N_EDGES + 16 * EPW - 1) / (16 * EPW), 512>>>(node, edge_index,
                                                              edge_attr, out);
    // graphnorm
    k_stats<<<(N_NODES + NODES_PER_BLOCK - 1) / NODES_PER_BLOCK, HIDDEN>>>(out, batch_ptr);
    k_meanvar<<<(NUM_GRAPHS * HIDDEN + 255) / 256, 256>>>(mean_scale, weight);
    {
        int threads = 256;
        int blocks = (int)((NH4 / 2 + threads - 1) / threads);   // 2 float4/thread
        k_final<<<blocks, threads>>>((float4*)out, batch_ptr, (const float4*)bias);
    }
}

// round 15
// speedup vs baseline: 1.1244x; 1.0409x over previous
#include <cuda_runtime.h>
#include <stdint.h>

#define N_NODES   50000
#define N_EDGES   640000
#define HIDDEN    128
#define NUM_GRAPHS 50
#define EPS       1e-5f
#define NODES_PER_BLOCK 64
#define EPW       4            // edges per warp in scatter (measured optimum)

static_assert(N_EDGES % EPW == 0, "scatter assumes N_EDGES divisible by EPW");

// Scratch (no allocations allowed)
__device__ float g_deg[N_NODES];                 // raw degree
__device__ float g_stat[NUM_GRAPHS * HIDDEN];    // sum, then mu = mean*mean_scale
__device__ float g_stat2[NUM_GRAPHS * HIDDEN];   // sumsq, then A = invstd*weight
__device__ int   g_cnt[NUM_GRAPHS];
__device__ int   g_is64;                         // 1 = int64 indices, 0 = int32

__device__ __forceinline__ int load_idx(const void* p, int i, int is64, int hi)
{
    long long v = is64 ? ((const long long*)p)[i] : (long long)((const int*)p)[i];
    if (v < 0) v = 0;
    if (v > hi) v = hi;
    return (int)v;
}

__device__ __forceinline__ void red_add_v4(float* dst, float4 v)
{
    asm volatile("red.global.add.v4.f32 [%0], {%1,%2,%3,%4};"
                 :: "l"(dst), "f"(v.x), "f"(v.y), "f"(v.z), "f"(v.w) : "memory");
}

// ---------------- init: out = node (float4), zero scratch, detect dtype ----------------
__global__ void k_init(const float4* __restrict__ node, float4* __restrict__ out,
                       const int* __restrict__ ei32)
{
    if (blockIdx.x == 0) {
        int nz = 0;
        for (int k = threadIdx.x; k < 4096; k += blockDim.x)
            if (ei32[2 * k + 1] != 0) nz = 1;
        int any = __syncthreads_count(nz);
        if (threadIdx.x == 0) g_is64 = (any == 0) ? 1 : 0;
    }
    int64_t total = (int64_t)N_NODES * HIDDEN / 4;
    int64_t stride = (int64_t)gridDim.x * blockDim.x;
    for (int64_t j = (int64_t)blockIdx.x * blockDim.x + threadIdx.x; j < total; j += stride) {
        out[j] = node[j];
        if (j < N_NODES) g_deg[j] = 0.0f;
        if (j < NUM_GRAPHS * HIDDEN) { g_stat[j] = 0.0f; g_stat2[j] = 0.0f; }
        if (j < NUM_GRAPHS) g_cnt[j] = 0;
    }
}

// ---------------- degree: deg[col] += edge_attr (4 edges/thread) ----------------
__global__ void k_deg(const void* __restrict__ ei, const float* __restrict__ ea)
{
    int is64 = g_is64;
    int base = (blockIdx.x * blockDim.x + threadIdx.x) * 4;
    #pragma unroll
    for (int k = 0; k < 4; k++) {
        int e = base + k;
        if (e < N_EDGES) {
            int c = load_idx(ei, N_EDGES + e, is64, N_NODES - 1);
            atomicAdd(&g_deg[c], ea[e]);
        }
    }
}

// ---------------- scatter: 4 edges per warp (measured optimum), v4 red ----------------
__global__ void k_scatter(const float* __restrict__ node,
                          const void* __restrict__ ei,
                          const float* __restrict__ ea,
                          float* __restrict__ out)
{
    int is64 = g_is64;
    int lane = threadIdx.x & 31;
    int w = blockIdx.x * (blockDim.x >> 5) + (threadIdx.x >> 5);
    int e0 = w * EPW;
    if (e0 >= N_EDGES) return;     // N_EDGES % EPW == 0: all surviving warps full

    int r[EPW], c[EPW];
    float wt[EPW];
    #pragma unroll
    for (int k = 0; k < EPW; k++) {
        r[k] = load_idx(ei, e0 + k, is64, N_NODES - 1);
        c[k] = load_idx(ei, N_EDGES + e0 + k, is64, N_NODES - 1);
    }
    #pragma unroll
    for (int k = 0; k < EPW; k++) {
        float dr = g_deg[r[k]], dc = g_deg[c[k]];
        float ir = dr > 0.0f ? rsqrtf(dr) : 0.0f;
        float ic = dc > 0.0f ? rsqrtf(dc) : 0.0f;
        wt[k] = ir * ea[e0 + k] * ic;
    }

    float4 v[EPW];
    #pragma unroll
    for (int k = 0; k < EPW; k++)
        v[k] = reinterpret_cast<const float4*>(node + (size_t)r[k] * HIDDEN)[lane];
    #pragma unroll
    for (int k = 0; k < EPW; k++) {
        v[k].x *= wt[k]; v[k].y *= wt[k]; v[k].z *= wt[k]; v[k].w *= wt[k];
        red_add_v4(out + (size_t)c[k] * HIDDEN + lane * 4, v[k]);
    }
}

// ---------------- stats: per-(graph,ch) sum & sumsq, register-accumulated ----------------
__global__ void k_stats(const float* __restrict__ out,
                        const void* __restrict__ batch_ptr)
{
    int is64 = g_is64;
    int ch = threadIdx.x;                       // 0..127
    int n0 = blockIdx.x * NODES_PER_BLOCK;
    int n1 = n0 + NODES_PER_BLOCK;
    if (n1 > N_NODES) n1 = N_NODES;
    if (n0 >= n1) return;

    int   g   = load_idx(batch_ptr, n0, is64, NUM_GRAPHS - 1);
    float s   = 0.0f, s2 = 0.0f;
    int   run = 0;

    for (int n = n0; n < n1; n++) {
        int gn = load_idx(batch_ptr, n, is64, NUM_GRAPHS - 1);
        if (gn != g) {
            atomicAdd(&g_stat[g * HIDDEN + ch], s);
            atomicAdd(&g_stat2[g * HIDDEN + ch], s2);
            if (ch == 0) atomicAdd(&g_cnt[g], run);
            s = 0.0f; s2 = 0.0f; run = 0; g = gn;
        }
        float v = out[(size_t)n * HIDDEN + ch];
        s += v; s2 += v * v; run++;
    }
    atomicAdd(&g_stat[g * HIDDEN + ch], s);
    atomicAdd(&g_stat2[g * HIDDEN + ch], s2);
    if (ch == 0) atomicAdd(&g_cnt[g], run);
}

// ---------------- meanvar: mu = mean*ms, A = rsqrt(var+eps)*weight ----------------
__global__ void k_meanvar(const float* __restrict__ mean_scale,
                          const float* __restrict__ weight)
{
    int i = blockIdx.x * blockDim.x + threadIdx.x;
    if (i < NUM_GRAPHS * HIDDEN) {
        int g = i >> 7, ch = i & 127;
        float cnt  = fmaxf((float)g_cnt[g], 1.0f);
        float mean = g_stat[i] / cnt;
        float e2   = g_stat2[i] / cnt;
        float ms   = mean_scale[ch];
        float var  = fmaxf(e2 - mean * mean * ms * (2.0f - ms), 0.0f);
        g_stat[i]  = mean * ms;
        g_stat2[i] = rsqrtf(var + EPS) * weight[ch];
    }
}

// ---------------- final: out = relu((h - mu) * A + bias), float4, exact grid ----------------
__global__ void k_final(float4* __restrict__ out,
                        const void* __restrict__ batch_ptr,
                        const float4* __restrict__ bias4)
{
    int is64 = g_is64;
    int64_t j = (int64_t)blockIdx.x * blockDim.x + threadIdx.x;
    if (j >= (int64_t)N_NODES * (HIDDEN / 4)) return;
    const float4* mu4 = (const float4*)g_stat;
    const float4* A4  = (const float4*)g_stat2;
    int n  = (int)(j >> 5);
    int c4 = (int)(j & 31);
    int g  = load_idx(batch_ptr, n, is64, NUM_GRAPHS - 1);
    float4 h  = out[j];
    float4 mu = mu4[g * 32 + c4];
    float4 A  = A4[g * 32 + c4];
    float4 b  = bias4[c4];
    h.x = fmaxf((h.x - mu.x) * A.x + b.x, 0.0f);
    h.y = fmaxf((h.y - mu.y) * A.y + b.y, 0.0f);
    h.z = fmaxf((h.z - mu.z) * A.z + b.z, 0.0f);
    h.w = fmaxf((h.w - mu.w) * A.w + b.w, 0.0f);
    out[j] = h;
}

extern "C" void kernel_launch(void* const* d_in, const int* in_sizes, int n_in,
                              void* d_out, int out_size)
{
    // Resolve inputs by element count.
    int idx_node = -1, idx_ei = -1, idx_ea = -1, idx_bp = -1;
    int idx128[3]; int n128 = 0;
    for (int i = 0; i < n_in; i++) {
        switch (in_sizes[i]) {
            case N_NODES * HIDDEN:  idx_node = i; break;
            case 2 * N_EDGES:       idx_ei   = i; break;
            case N_EDGES:           idx_ea   = i; break;
            case N_NODES:           idx_bp   = i; break;
            case HIDDEN:            if (n128 < 3) idx128[n128++] = i; break;
        }
    }
    int idx_w, idx_b, idx_ms;
    if (idx_node >= 0 && idx_bp >= 0 && idx_node > idx_bp) {
        idx_b = idx128[0]; idx_ms = idx128[1]; idx_w = idx128[2];   // alphabetical
    } else {
        idx_w = idx128[0]; idx_b = idx128[1]; idx_ms = idx128[2];   // declaration
    }

    const float* node       = (const float*)d_in[idx_node];
    const void*  edge_index = d_in[idx_ei];
    const float* edge_attr  = (const float*)d_in[idx_ea];
    const void*  batch_ptr  = d_in[idx_bp];
    const float* weight     = (const float*)d_in[idx_w];
    const float* bias       = (const float*)d_in[idx_b];
    const float* mean_scale = (const float*)d_in[idx_ms];
    float* out = (float*)d_out;

    const int64_t NH4 = (int64_t)N_NODES * HIDDEN / 4;   // 1,600,000

    // init + dtype detect
    {
        int threads = 256;
        int blocks = (int)((NH4 + threads - 1) / threads);
        if (blocks > 8192) blocks = 8192;
        k_init<<<blocks, threads>>>((const float4*)node, (float4*)out,
                                    (const int*)edge_index);
    }
    // degree (4 edges/thread)
    k_deg<<<(N_EDGES / 4 + 255) / 256, 256>>>(edge_index, edge_attr);
    // scatter: 256 threads = 8 warps = 32 edges per block (smoother wave tail)
    k_scatter<<<(N_EDGES + 8 * EPW - 1) / (8 * EPW), 256>>>(node, edge_index,
                                                            edge_attr, out);
    // graphnorm
    k_stats<<<(N_NODES + NODES_PER_BLOCK - 1) / NODES_PER_BLOCK, HIDDEN>>>(out, batch_ptr);
    k_meanvar<<<(NUM_GRAPHS * HIDDEN + 255) / 256, 256>>>(mean_scale, weight);
    {
        int threads = 256;
        int blocks = (int)((NH4 + threads - 1) / threads);   // exact cover
        k_final<<<blocks, threads>>>((float4*)out, batch_ptr, (const float4*)bias);
    }
}